// round 1
// baseline (speedup 1.0000x reference)
#include <cuda_runtime.h>
#include <math.h>

#define B_   4
#define L_   2048
#define NH_  16
#define DH_  64
#define DM_  1024
#define M_   (B_*L_)   // 8192

// Scratch (static device globals -- no allocation APIs allowed)
__device__ float g_qh[(size_t)B_ * NH_ * L_ * DH_];   // [B,H,L,64]
__device__ float g_kh[(size_t)B_ * NH_ * L_ * DH_];
__device__ float g_vh[(size_t)B_ * NH_ * L_ * DH_];
__device__ float g_ao[(size_t)M_ * DM_];              // [B*L, H*64]

// ---------------------------------------------------------------------------
// SGEMM: C[8192,1024] = A[8192,1024] @ W[1024,1024]
// MODE 0: write head-major layout  C[((b*16+h)*2048+l)*64+d]
// MODE 1: write row-major + residual
// 128x128 block tile, BK=16, 8x8 per thread, 256 threads, reg-prefetch.
// ---------------------------------------------------------------------------
template <int MODE>
__global__ void __launch_bounds__(256) gemm8192(const float* __restrict__ A,
                                                const float* __restrict__ W,
                                                float* __restrict__ C,
                                                const float* __restrict__ res)
{
    constexpr int N = 1024, K = 1024;
    constexpr int BM = 128, BN = 128, BK = 16;
    __shared__ float As[BK][BM];   // A transposed: As[k][m]
    __shared__ float Bs[BK][BN];

    const int tid  = threadIdx.x;
    const int tx   = tid & 15;
    const int ty   = tid >> 4;
    const int row0 = blockIdx.y * BM;
    const int col0 = blockIdx.x * BN;
    const float* Ab = A + (size_t)row0 * K;
    const float* Wb = W + col0;

    float4 a_ld[2], b_ld[2];
    float acc[8][8];
#pragma unroll
    for (int i = 0; i < 8; i++)
#pragma unroll
        for (int j = 0; j < 8; j++) acc[i][j] = 0.f;

    auto gload = [&](int kt) {
#pragma unroll
        for (int u = 0; u < 2; u++) {
            int vv = tid + u * 256;                       // 0..511
            int ar = vv >> 2;                             // 0..127
            int ac = (vv & 3) << 2;                       // 0,4,8,12
            a_ld[u] = *reinterpret_cast<const float4*>(Ab + (size_t)ar * K + kt * BK + ac);
            int br = vv >> 5;                             // 0..15
            int bc = (vv & 31) << 2;                      // 0..124
            b_ld[u] = *reinterpret_cast<const float4*>(Wb + (size_t)(kt * BK + br) * N + bc);
        }
    };
    auto sstore = [&]() {
#pragma unroll
        for (int u = 0; u < 2; u++) {
            int vv = tid + u * 256;
            int ar = vv >> 2;
            int ac = (vv & 3) << 2;
            As[ac + 0][ar] = a_ld[u].x;
            As[ac + 1][ar] = a_ld[u].y;
            As[ac + 2][ar] = a_ld[u].z;
            As[ac + 3][ar] = a_ld[u].w;
            *reinterpret_cast<float4*>(&Bs[vv >> 5][(vv & 31) << 2]) = b_ld[u];
        }
    };
    auto micro = [&]() {
#pragma unroll
        for (int kk = 0; kk < BK; kk++) {
            float4 a0 = *reinterpret_cast<const float4*>(&As[kk][ty * 8]);
            float4 a1 = *reinterpret_cast<const float4*>(&As[kk][ty * 8 + 4]);
            float4 b0 = *reinterpret_cast<const float4*>(&Bs[kk][tx * 8]);
            float4 b1 = *reinterpret_cast<const float4*>(&Bs[kk][tx * 8 + 4]);
            float av[8] = {a0.x, a0.y, a0.z, a0.w, a1.x, a1.y, a1.z, a1.w};
            float bv[8] = {b0.x, b0.y, b0.z, b0.w, b1.x, b1.y, b1.z, b1.w};
#pragma unroll
            for (int i = 0; i < 8; i++)
#pragma unroll
                for (int j = 0; j < 8; j++) acc[i][j] = fmaf(av[i], bv[j], acc[i][j]);
        }
    };

    gload(0);
    sstore();
    __syncthreads();
    constexpr int KT = K / BK;   // 64
#pragma unroll 1
    for (int kt = 1; kt < KT; kt++) {
        gload(kt);       // prefetch next slab (global latency overlaps compute)
        micro();         // consume smem slab kt-1
        __syncthreads();
        sstore();
        __syncthreads();
    }
    micro();

    if (MODE == 0) {
        // head-major epilogue: n = h*64+d, tile cols never cross a head boundary
#pragma unroll
        for (int i = 0; i < 8; i++) {
            int m  = row0 + ty * 8 + i;
            int bb = m >> 11;         // /2048
            int l  = m & 2047;
            int n  = col0 + tx * 8;
            int h  = n >> 6;
            int d  = n & 63;
            float* dst = C + (((size_t)bb * NH_ + h) * L_ + l) * DH_ + d;
            *reinterpret_cast<float4*>(dst)     = make_float4(acc[i][0], acc[i][1], acc[i][2], acc[i][3]);
            *reinterpret_cast<float4*>(dst + 4) = make_float4(acc[i][4], acc[i][5], acc[i][6], acc[i][7]);
        }
    } else {
#pragma unroll
        for (int i = 0; i < 8; i++) {
            int m = row0 + ty * 8 + i;
            size_t off = (size_t)m * N + col0 + tx * 8;
            float4 r0 = *reinterpret_cast<const float4*>(res + off);
            float4 r1 = *reinterpret_cast<const float4*>(res + off + 4);
            *reinterpret_cast<float4*>(C + off) =
                make_float4(acc[i][0] + r0.x, acc[i][1] + r0.y, acc[i][2] + r0.z, acc[i][3] + r0.w);
            *reinterpret_cast<float4*>(C + off + 4) =
                make_float4(acc[i][4] + r1.x, acc[i][5] + r1.y, acc[i][6] + r1.z, acc[i][7] + r1.w);
        }
    }
}

// ---------------------------------------------------------------------------
// Flash attention: one CTA = 64 q-rows of one (b,h). K-tiles of 64.
// 16x16 threads, 4x4 microtile for both S = Q K^T and O += P V.
// Smem: qs (Q^T), kps (K^T, reused as P^T after S phase), vs. 48 KB total.
// ---------------------------------------------------------------------------
__global__ void __launch_bounds__(256) attn_kernel(const int* __restrict__ mask)
{
    __shared__ float qs[64 * 64];    // qs[d*64 + qrow]
    __shared__ float kps[64 * 64];   // K phase: [d*64 + kcol]; P phase: [kcol*64 + qrow]
    __shared__ float vs[64 * 64];    // vs[kpos*64 + d]

    const int tid = threadIdx.x;
    const int tx  = tid & 15;
    const int ty  = tid >> 4;
    const int bh  = blockIdx.y;
    const int bb  = bh >> 4;
    const int hh  = bh & 15;
    const int q0  = blockIdx.x * 64;

    const float* Q  = g_qh + (size_t)bh * L_ * DH_;
    const float* Kp = g_kh + (size_t)bh * L_ * DH_;
    const float* Vp = g_vh + (size_t)bh * L_ * DH_;

    // load Q tile, transposed into smem
#pragma unroll
    for (int u = 0; u < 4; u++) {
        int vv = tid + u * 256;       // 0..1023
        int r  = vv >> 4;             // 0..63
        int d  = (vv & 15) << 2;      // 0..60
        float4 t = *reinterpret_cast<const float4*>(Q + (size_t)(q0 + r) * DH_ + d);
        qs[(d + 0) * 64 + r] = t.x;
        qs[(d + 1) * 64 + r] = t.y;
        qs[(d + 2) * 64 + r] = t.z;
        qs[(d + 3) * 64 + r] = t.w;
    }

    float o[4][4];
    float m_i[4], l_i[4];
#pragma unroll
    for (int i = 0; i < 4; i++) {
        m_i[i] = -1e30f;
        l_i[i] = 0.f;
#pragma unroll
        for (int j = 0; j < 4; j++) o[i][j] = 0.f;
    }
    __syncthreads();

#pragma unroll 1
    for (int kt = 0; kt < L_ / 64; kt++) {
        const int k0 = kt * 64;
        // load K (transposed) and V (natural)
#pragma unroll
        for (int u = 0; u < 4; u++) {
            int vv = tid + u * 256;
            int r  = vv >> 4;
            int d  = (vv & 15) << 2;
            float4 t = *reinterpret_cast<const float4*>(Kp + (size_t)(k0 + r) * DH_ + d);
            kps[(d + 0) * 64 + r] = t.x;
            kps[(d + 1) * 64 + r] = t.y;
            kps[(d + 2) * 64 + r] = t.z;
            kps[(d + 3) * 64 + r] = t.w;
            float4 w = *reinterpret_cast<const float4*>(Vp + (size_t)(k0 + r) * DH_ + d);
            *reinterpret_cast<float4*>(&vs[r * 64 + d]) = w;
        }
        __syncthreads();

        // S = Q K^T (4x4 per thread)
        float s[4][4];
#pragma unroll
        for (int i = 0; i < 4; i++)
#pragma unroll
            for (int j = 0; j < 4; j++) s[i][j] = 0.f;
#pragma unroll 8
        for (int d = 0; d < 64; d++) {
            float4 aq = *reinterpret_cast<const float4*>(&qs[d * 64 + ty * 4]);
            float4 bk = *reinterpret_cast<const float4*>(&kps[d * 64 + tx * 4]);
            float av[4] = {aq.x, aq.y, aq.z, aq.w};
            float bv[4] = {bk.x, bk.y, bk.z, bk.w};
#pragma unroll
            for (int i = 0; i < 4; i++)
#pragma unroll
                for (int j = 0; j < 4; j++) s[i][j] = fmaf(av[i], bv[j], s[i][j]);
        }

        // scale-then-mask, matching reference: where(mask==0, -1e9, s/sqrt(dk))
#pragma unroll
        for (int i = 0; i < 4; i++) {
            int row = q0 + ty * 4 + i;
            int4 mv = *reinterpret_cast<const int4*>(
                mask + ((size_t)(bb * L_ + row)) * L_ + k0 + tx * 4);
            s[i][0] = mv.x ? s[i][0] * 0.125f : -1e9f;
            s[i][1] = mv.y ? s[i][1] * 0.125f : -1e9f;
            s[i][2] = mv.z ? s[i][2] * 0.125f : -1e9f;
            s[i][3] = mv.w ? s[i][3] * 0.125f : -1e9f;
        }

        // online softmax; row stats reduced across the 16-lane tx group
#pragma unroll
        for (int i = 0; i < 4; i++) {
            float mx = fmaxf(fmaxf(s[i][0], s[i][1]), fmaxf(s[i][2], s[i][3]));
            mx = fmaxf(mx, __shfl_xor_sync(0xffffffffu, mx, 1));
            mx = fmaxf(mx, __shfl_xor_sync(0xffffffffu, mx, 2));
            mx = fmaxf(mx, __shfl_xor_sync(0xffffffffu, mx, 4));
            mx = fmaxf(mx, __shfl_xor_sync(0xffffffffu, mx, 8));
            float m_new = fmaxf(m_i[i], mx);
            float corr  = __expf(m_i[i] - m_new);
            m_i[i] = m_new;
            float rs = 0.f;
#pragma unroll
            for (int j = 0; j < 4; j++) {
                s[i][j] = __expf(s[i][j] - m_new);
                rs += s[i][j];
            }
            rs += __shfl_xor_sync(0xffffffffu, rs, 1);
            rs += __shfl_xor_sync(0xffffffffu, rs, 2);
            rs += __shfl_xor_sync(0xffffffffu, rs, 4);
            rs += __shfl_xor_sync(0xffffffffu, rs, 8);
            l_i[i] = l_i[i] * corr + rs;
#pragma unroll
            for (int j = 0; j < 4; j++) o[i][j] *= corr;
        }

        __syncthreads();   // all threads done reading kps as K^T
        // write P^T over the K^T buffer (register transpose -> float4 stores)
#pragma unroll
        for (int j = 0; j < 4; j++)
            *reinterpret_cast<float4*>(&kps[(tx * 4 + j) * 64 + ty * 4]) =
                make_float4(s[0][j], s[1][j], s[2][j], s[3][j]);
        __syncthreads();

        // O += P V
#pragma unroll 8
        for (int j = 0; j < 64; j++) {
            float4 ap = *reinterpret_cast<const float4*>(&kps[j * 64 + ty * 4]);
            float4 bw = *reinterpret_cast<const float4*>(&vs[j * 64 + tx * 4]);
            float av[4] = {ap.x, ap.y, ap.z, ap.w};
            float bv[4] = {bw.x, bw.y, bw.z, bw.w};
#pragma unroll
            for (int i = 0; i < 4; i++)
#pragma unroll
                for (int jj = 0; jj < 4; jj++) o[i][jj] = fmaf(av[i], bv[jj], o[i][jj]);
        }
        __syncthreads();
    }

    // normalize and write [B*L, H*64]
#pragma unroll
    for (int i = 0; i < 4; i++) {
        float inv = __fdividef(1.f, l_i[i]);
        int row = q0 + ty * 4 + i;
        *reinterpret_cast<float4*>(
            &g_ao[((size_t)(bb * L_ + row)) * DM_ + hh * DH_ + tx * 4]) =
            make_float4(o[i][0] * inv, o[i][1] * inv, o[i][2] * inv, o[i][3] * inv);
    }
}

// ---------------------------------------------------------------------------
extern "C" void kernel_launch(void* const* d_in, const int* in_sizes, int n_in,
                              void* d_out, int out_size)
{
    const float* q    = (const float*)d_in[0];
    const float* k    = (const float*)d_in[1];
    const float* v    = (const float*)d_in[2];
    const int*   mask = (const int*)d_in[3];
    const float* w_qs = (const float*)d_in[4];
    const float* w_ks = (const float*)d_in[5];
    const float* w_vs = (const float*)d_in[6];
    const float* w_fc = (const float*)d_in[7];
    float* out = (float*)d_out;

    float *qh, *kh, *vh, *ao;
    cudaGetSymbolAddress((void**)&qh, g_qh);
    cudaGetSymbolAddress((void**)&kh, g_kh);
    cudaGetSymbolAddress((void**)&vh, g_vh);
    cudaGetSymbolAddress((void**)&ao, g_ao);

    dim3 ggrid(DM_ / 128, M_ / 128);   // (8, 64)
    gemm8192<0><<<ggrid, 256>>>(q, w_qs, qh, nullptr);
    gemm8192<0><<<ggrid, 256>>>(k, w_ks, kh, nullptr);
    gemm8192<0><<<ggrid, 256>>>(v, w_vs, vh, nullptr);
    attn_kernel<<<dim3(L_ / 64, B_ * NH_), 256>>>(mask);
    gemm8192<1><<<ggrid, 256>>>(ao, w_fc, out, q);
}

// round 2
// speedup vs baseline: 2.1338x; 2.1338x over previous
#include <cuda_runtime.h>
#include <math.h>
#include <stdint.h>

#define B_   4
#define L_   2048
#define NH_  16
#define DH_  64
#define DM_  1024
#define M_   (B_*L_)   // 8192

// Scratch (static device globals -- no allocation APIs allowed)
__device__ float g_qh[(size_t)B_ * NH_ * L_ * DH_];   // [B,H,L,64]
__device__ float g_kh[(size_t)B_ * NH_ * L_ * DH_];
__device__ float g_vh[(size_t)B_ * NH_ * L_ * DH_];
__device__ float g_ao[(size_t)M_ * DM_];              // [B*L, H*64]
__device__ uint32_t g_mb[(size_t)M_ * (L_ / 32)];     // bit-packed mask [B*LQ][64 words]

// ---------------------------------------------------------------------------
// helpers
// ---------------------------------------------------------------------------
__device__ __forceinline__ uint32_t f2tf(float f) {
    uint32_t u;
    asm volatile("cvt.rna.tf32.f32 %0, %1;" : "=r"(u) : "f"(f));
    return u;
}
__device__ __forceinline__ float f2tff(float f) { return __uint_as_float(f2tf(f)); }

__device__ __forceinline__ uint32_t smem_u32(const void* p) {
    return (uint32_t)__cvta_generic_to_shared(p);
}

__device__ __forceinline__ void ldsm4(uint32_t addr, uint32_t r[4]) {
    asm volatile("ldmatrix.sync.aligned.m8n8.x4.shared.b16 {%0,%1,%2,%3}, [%4];"
                 : "=r"(r[0]), "=r"(r[1]), "=r"(r[2]), "=r"(r[3]) : "r"(addr));
}

__device__ __forceinline__ void mma_tf32(float d[4], const uint32_t a[4],
                                         uint32_t b0, uint32_t b1) {
    asm volatile(
        "mma.sync.aligned.m16n8k8.row.col.f32.tf32.tf32.f32 "
        "{%0,%1,%2,%3},{%4,%5,%6,%7},{%8,%9},{%0,%1,%2,%3};"
        : "+f"(d[0]), "+f"(d[1]), "+f"(d[2]), "+f"(d[3])
        : "r"(a[0]), "r"(a[1]), "r"(a[2]), "r"(a[3]), "r"(b0), "r"(b1));
}

// ---------------------------------------------------------------------------
// mask bit-pack: 64MB int32 -> 2MB bitmask (word w bit j = mask[32w+j] != 0)
// ---------------------------------------------------------------------------
__global__ void __launch_bounds__(256) maskpack(const int* __restrict__ m) {
    int gw   = (blockIdx.x * blockDim.x + threadIdx.x) >> 5;
    int lane = threadIdx.x & 31;
    size_t base = (size_t)gw * 1024;
    uint32_t myw = 0;
#pragma unroll
    for (int j = 0; j < 32; j++) {
        int v = m[base + j * 32 + lane];
        uint32_t b = __ballot_sync(0xffffffffu, v != 0);
        if (lane == j) myw = b;
    }
    g_mb[(size_t)gw * 32 + lane] = myw;
}

// ---------------------------------------------------------------------------
// tf32 tensor-core GEMM: C[8192,1024] = A[8192,1024] @ W[1024,1024]
// MODE 0: write head-major  C[((b*16+h)*2048+l)*64+d]
// MODE 1: write row-major + residual
// 128x128 tile, BK=16, 8 warps (2x4), warp tile 64x32, m16n8k8 via ldmatrix.
// ---------------------------------------------------------------------------
template <int MODE>
__global__ void __launch_bounds__(256) gemm_tc(const float* __restrict__ A,
                                               const float* __restrict__ W,
                                               float* __restrict__ C,
                                               const float* __restrict__ res)
{
    constexpr int N = 1024, K = 1024;
    constexpr int SA = 20, SB = 20;       // padded strides (floats)
    __shared__ __align__(16) float As[128 * SA];   // [m][k] rows m, k contiguous
    __shared__ __align__(16) float Bs[128 * SB];   // [n][k] rows n, k contiguous

    const int tid  = threadIdx.x;
    const int lane = tid & 31;
    const int warp = tid >> 5;
    const int mw   = warp >> 2;           // 0..1
    const int nw   = warp & 3;            // 0..3
    const int jm   = lane >> 3;           // ldsm matrix id 0..3
    const int qj   = lane & 7;
    const int g    = lane >> 2;
    const int tig  = lane & 3;
    const int row0 = blockIdx.y * 128;
    const int col0 = blockIdx.x * 128;

    float4 a_ld[2], b_ld[2];
    float acc[4][4][4];
#pragma unroll
    for (int mi = 0; mi < 4; mi++)
#pragma unroll
        for (int ni = 0; ni < 4; ni++)
#pragma unroll
            for (int r = 0; r < 4; r++) acc[mi][ni][r] = 0.f;

    auto gload = [&](int kt) {
#pragma unroll
        for (int u = 0; u < 2; u++) {
            int vv = tid + u * 256;
            int ar = vv >> 2;
            int ac = (vv & 3) << 2;
            a_ld[u] = *reinterpret_cast<const float4*>(A + (size_t)(row0 + ar) * K + kt * 16 + ac);
            int br = vv >> 5;
            int bc = (vv & 31) << 2;
            b_ld[u] = *reinterpret_cast<const float4*>(W + (size_t)(kt * 16 + br) * N + col0 + bc);
        }
    };
    auto sstore = [&]() {
#pragma unroll
        for (int u = 0; u < 2; u++) {
            int vv = tid + u * 256;
            int ar = vv >> 2;
            int ac = (vv & 3) << 2;
            *reinterpret_cast<float4*>(&As[ar * SA + ac]) =
                make_float4(f2tff(a_ld[u].x), f2tff(a_ld[u].y), f2tff(a_ld[u].z), f2tff(a_ld[u].w));
            int br = vv >> 5;
            int bc = (vv & 31) << 2;
            Bs[(bc + 0) * SB + br] = f2tff(b_ld[u].x);
            Bs[(bc + 1) * SB + br] = f2tff(b_ld[u].y);
            Bs[(bc + 2) * SB + br] = f2tff(b_ld[u].z);
            Bs[(bc + 3) * SB + br] = f2tff(b_ld[u].w);
        }
    };

    const uint32_t sA = smem_u32(As);
    const uint32_t sB = smem_u32(Bs);

    auto compute = [&]() {
#pragma unroll
        for (int ks = 0; ks < 2; ks++) {
            const int k0 = ks * 8;
            uint32_t a[4][4];
#pragma unroll
            for (int mi = 0; mi < 4; mi++) {
                int r = mw * 64 + mi * 16 + ((jm & 1) << 3) + qj;
                int c = k0 + ((jm >> 1) << 2);
                ldsm4(sA + (r * SA + c) * 4, a[mi]);
            }
            uint32_t b[2][4];
#pragma unroll
            for (int p = 0; p < 2; p++) {
                int n = nw * 32 + (p << 4) + ((jm >> 1) << 3) + qj;
                int c = k0 + ((jm & 1) << 2);
                ldsm4(sB + (n * SB + c) * 4, b[p]);
            }
#pragma unroll
            for (int mi = 0; mi < 4; mi++) {
                mma_tf32(acc[mi][0], a[mi], b[0][0], b[0][1]);
                mma_tf32(acc[mi][1], a[mi], b[0][2], b[0][3]);
                mma_tf32(acc[mi][2], a[mi], b[1][0], b[1][1]);
                mma_tf32(acc[mi][3], a[mi], b[1][2], b[1][3]);
            }
        }
    };

    gload(0);
    sstore();
    __syncthreads();
    constexpr int KT = K / 16;   // 64
#pragma unroll 1
    for (int kt = 1; kt < KT; kt++) {
        gload(kt);
        compute();
        __syncthreads();
        sstore();
        __syncthreads();
    }
    compute();

    // epilogue
#pragma unroll
    for (int mi = 0; mi < 4; mi++) {
#pragma unroll
        for (int ni = 0; ni < 4; ni++) {
            int m = row0 + mw * 64 + mi * 16 + g;
            int n = col0 + nw * 32 + ni * 8 + 2 * tig;
            if (MODE == 0) {
                int bb = m >> 11, l = m & 2047;
                int h = n >> 6, d = n & 63;
                float* dst = C + (((size_t)bb * NH_ + h) * L_ + l) * DH_ + d;
                *reinterpret_cast<float2*>(dst) = make_float2(acc[mi][ni][0], acc[mi][ni][1]);
                *reinterpret_cast<float2*>(dst + (size_t)8 * DH_) =
                    make_float2(acc[mi][ni][2], acc[mi][ni][3]);
            } else {
                size_t off = (size_t)m * N + n;
                float2 r0 = *reinterpret_cast<const float2*>(res + off);
                float2 r1 = *reinterpret_cast<const float2*>(res + off + (size_t)8 * N);
                *reinterpret_cast<float2*>(C + off) =
                    make_float2(acc[mi][ni][0] + r0.x, acc[mi][ni][1] + r0.y);
                *reinterpret_cast<float2*>(C + off + (size_t)8 * N) =
                    make_float2(acc[mi][ni][2] + r1.x, acc[mi][ni][3] + r1.y);
            }
        }
    }
}

// ---------------------------------------------------------------------------
// Flash attention on tensor cores. CTA = 64 q-rows of one (b,h); 4 warps,
// warp = 16 rows. K-tiles of 64. S and P*V both m16n8k8 tf32.
// Smem: Qs[64][68] + KPs[64][68] (K, reused as P) + Vs[64][68] = 52224 B.
// ---------------------------------------------------------------------------
#define ATTN_SMEM (3 * 64 * 68 * 4)

__global__ void __launch_bounds__(128) attn_tc(const uint32_t* __restrict__ mb)
{
    extern __shared__ __align__(16) float sm[];
    float* Qs  = sm;                 // [q][d]    stride 68
    float* KPs = sm + 64 * 68;       // [kpos][d] then [q][kpos]
    float* Vs  = sm + 2 * 64 * 68;   // [kpos][d]

    const int tid  = threadIdx.x;
    const int lane = tid & 31;
    const int w    = tid >> 5;       // warp 0..3
    const int g    = lane >> 2;
    const int tig  = lane & 3;
    const int jm   = lane >> 3;
    const int qj   = lane & 7;
    const int bh   = blockIdx.y;
    const int bb   = bh >> 4;
    const int hh   = bh & 15;
    const int q0   = blockIdx.x * 64;

    const float* Qg = g_qh + (size_t)bh * L_ * DH_;
    const float* Kg = g_kh + (size_t)bh * L_ * DH_;
    const float* Vg = g_vh + (size_t)bh * L_ * DH_;

    // load Q tile (convert to tf32 bits)
#pragma unroll
    for (int u = 0; u < 8; u++) {
        int vv = tid + u * 128;
        int r  = vv >> 4;
        int c  = (vv & 15) << 2;
        float4 t = *reinterpret_cast<const float4*>(Qg + (size_t)(q0 + r) * DH_ + c);
        *reinterpret_cast<float4*>(&Qs[r * 68 + c]) =
            make_float4(f2tff(t.x), f2tff(t.y), f2tff(t.z), f2tff(t.w));
    }

    float o[8][4];
    float m_i[2] = {-1e30f, -1e30f};
    float l_i[2] = {0.f, 0.f};
#pragma unroll
    for (int ni = 0; ni < 8; ni++)
#pragma unroll
        for (int r = 0; r < 4; r++) o[ni][r] = 0.f;

    const uint32_t sQ = smem_u32(Qs);
    const uint32_t sKP = smem_u32(KPs);

#pragma unroll 1
    for (int kt = 0; kt < L_ / 64; kt++) {
        const int k0g = kt * 64;
        // load K and V tiles
#pragma unroll
        for (int u = 0; u < 8; u++) {
            int vv = tid + u * 128;
            int r  = vv >> 4;
            int c  = (vv & 15) << 2;
            float4 tk = *reinterpret_cast<const float4*>(Kg + (size_t)(k0g + r) * DH_ + c);
            *reinterpret_cast<float4*>(&KPs[r * 68 + c]) =
                make_float4(f2tff(tk.x), f2tff(tk.y), f2tff(tk.z), f2tff(tk.w));
            float4 tv = *reinterpret_cast<const float4*>(Vg + (size_t)(k0g + r) * DH_ + c);
            *reinterpret_cast<float4*>(&Vs[r * 68 + c]) =
                make_float4(f2tff(tv.x), f2tff(tv.y), f2tff(tv.z), f2tff(tv.w));
        }
        __syncthreads();

        // S = Q K^T
        float s[8][4];
#pragma unroll
        for (int ni = 0; ni < 8; ni++)
#pragma unroll
            for (int r = 0; r < 4; r++) s[ni][r] = 0.f;
#pragma unroll
        for (int ks = 0; ks < 8; ks++) {
            const int k0 = ks * 8;
            uint32_t a[4];
            {
                int r = 16 * w + ((jm & 1) << 3) + qj;
                int c = k0 + ((jm >> 1) << 2);
                ldsm4(sQ + (r * 68 + c) * 4, a);
            }
#pragma unroll
            for (int p = 0; p < 4; p++) {
                uint32_t b[4];
                int n = (p << 4) + ((jm >> 1) << 3) + qj;
                int c = k0 + ((jm & 1) << 2);
                ldsm4(sKP + (n * 68 + c) * 4, b);
                mma_tf32(s[2 * p],     a, b[0], b[1]);
                mma_tf32(s[2 * p + 1], a, b[2], b[3]);
            }
        }

        // mask + scale (bitmask; reference order: scale then -1e9 fill)
        const int rlo = q0 + 16 * w + g;
        const uint32_t* mrow_lo = mb + ((size_t)(bb * L_) + rlo) * (L_ / 32) + kt * 2;
        const uint32_t* mrow_hi = mrow_lo + (size_t)8 * (L_ / 32);
        uint32_t wlo0 = mrow_lo[0], wlo1 = mrow_lo[1];
        uint32_t whi0 = mrow_hi[0], whi1 = mrow_hi[1];
#pragma unroll
        for (int ni = 0; ni < 8; ni++) {
            int c0 = ni * 8 + 2 * tig;
            int sh = c0 & 31;
            uint32_t wl = (ni < 4) ? wlo0 : wlo1;
            uint32_t wh = (ni < 4) ? whi0 : whi1;
            s[ni][0] = ((wl >> sh) & 1)       ? s[ni][0] * 0.125f : -1e9f;
            s[ni][1] = ((wl >> (sh + 1)) & 1) ? s[ni][1] * 0.125f : -1e9f;
            s[ni][2] = ((wh >> sh) & 1)       ? s[ni][2] * 0.125f : -1e9f;
            s[ni][3] = ((wh >> (sh + 1)) & 1) ? s[ni][3] * 0.125f : -1e9f;
        }

        // online softmax (row stats across the 4-lane tig group)
#pragma unroll
        for (int h = 0; h < 2; h++) {
            float mx = -1e30f;
#pragma unroll
            for (int ni = 0; ni < 8; ni++)
                mx = fmaxf(mx, fmaxf(s[ni][2 * h], s[ni][2 * h + 1]));
            mx = fmaxf(mx, __shfl_xor_sync(0xffffffffu, mx, 1));
            mx = fmaxf(mx, __shfl_xor_sync(0xffffffffu, mx, 2));
            float m_new = fmaxf(m_i[h], mx);
            float corr  = __expf(m_i[h] - m_new);
            m_i[h] = m_new;
            float sum = 0.f;
#pragma unroll
            for (int ni = 0; ni < 8; ni++) {
                s[ni][2 * h]     = __expf(s[ni][2 * h] - m_new);
                s[ni][2 * h + 1] = __expf(s[ni][2 * h + 1] - m_new);
                sum += s[ni][2 * h] + s[ni][2 * h + 1];
            }
            sum += __shfl_xor_sync(0xffffffffu, sum, 1);
            sum += __shfl_xor_sync(0xffffffffu, sum, 2);
            l_i[h] = l_i[h] * corr + sum;
#pragma unroll
            for (int ni = 0; ni < 8; ni++) {
                o[ni][2 * h]     *= corr;
                o[ni][2 * h + 1] *= corr;
            }
        }

        __syncthreads();   // all warps done reading KPs as K
        // write P over KPs (tf32 bits); each warp writes only its own 16 rows
#pragma unroll
        for (int ni = 0; ni < 8; ni++) {
            int c = ni * 8 + 2 * tig;
            *reinterpret_cast<float2*>(&KPs[(16 * w + g) * 68 + c]) =
                make_float2(f2tff(s[ni][0]), f2tff(s[ni][1]));
            *reinterpret_cast<float2*>(&KPs[(16 * w + g + 8) * 68 + c]) =
                make_float2(f2tff(s[ni][2]), f2tff(s[ni][3]));
        }
        __syncwarp();

        // O += P V   (A = P via ldmatrix; B = V via scalar LDS, 2-way conflicts)
#pragma unroll
        for (int ks = 0; ks < 8; ks++) {
            const int k0 = ks * 8;
            uint32_t a[4];
            {
                int r = 16 * w + ((jm & 1) << 3) + qj;
                int c = k0 + ((jm >> 1) << 2);
                ldsm4(sKP + (r * 68 + c) * 4, a);
            }
#pragma unroll
            for (int ni = 0; ni < 8; ni++) {
                uint32_t b0 = __float_as_uint(Vs[(k0 + tig) * 68 + ni * 8 + g]);
                uint32_t b1 = __float_as_uint(Vs[(k0 + tig + 4) * 68 + ni * 8 + g]);
                mma_tf32(o[ni], a, b0, b1);
            }
        }
        __syncthreads();   // before next tile overwrites KPs / Vs
    }

    // normalize and write [B*L, H*64]
#pragma unroll
    for (int h = 0; h < 2; h++) {
        float inv = __fdividef(1.f, l_i[h]);
        int row = q0 + 16 * w + g + 8 * h;
        float* dst = &g_ao[((size_t)(bb * L_ + row)) * DM_ + hh * DH_];
#pragma unroll
        for (int ni = 0; ni < 8; ni++) {
            *reinterpret_cast<float2*>(dst + ni * 8 + 2 * tig) =
                make_float2(o[ni][2 * h] * inv, o[ni][2 * h + 1] * inv);
        }
    }
}

// ---------------------------------------------------------------------------
extern "C" void kernel_launch(void* const* d_in, const int* in_sizes, int n_in,
                              void* d_out, int out_size)
{
    const float* q    = (const float*)d_in[0];
    const float* k    = (const float*)d_in[1];
    const float* v    = (const float*)d_in[2];
    const int*   mask = (const int*)d_in[3];
    const float* w_qs = (const float*)d_in[4];
    const float* w_ks = (const float*)d_in[5];
    const float* w_vs = (const float*)d_in[6];
    const float* w_fc = (const float*)d_in[7];
    float* out = (float*)d_out;

    float *qh, *kh, *vh, *ao;
    uint32_t* mbp;
    cudaGetSymbolAddress((void**)&qh, g_qh);
    cudaGetSymbolAddress((void**)&kh, g_kh);
    cudaGetSymbolAddress((void**)&vh, g_vh);
    cudaGetSymbolAddress((void**)&ao, g_ao);
    cudaGetSymbolAddress((void**)&mbp, g_mb);

    cudaFuncSetAttribute(attn_tc, cudaFuncAttributeMaxDynamicSharedMemorySize, ATTN_SMEM);

    // pack mask: 8192*64 words, 32 words per warp -> 16384 warps
    maskpack<<<2048, 256>>>(mask);

    dim3 ggrid(DM_ / 128, M_ / 128);   // (8, 64)
    gemm_tc<0><<<ggrid, 256>>>(q, w_qs, qh, nullptr);
    gemm_tc<0><<<ggrid, 256>>>(k, w_ks, kh, nullptr);
    gemm_tc<0><<<ggrid, 256>>>(v, w_vs, vh, nullptr);
    attn_tc<<<dim3(L_ / 64, B_ * NH_), 128, ATTN_SMEM>>>(mbp);
    gemm_tc<1><<<ggrid, 256>>>(ao, w_fc, out, q);
}